// round 5
// baseline (speedup 1.0000x reference)
#include <cuda_runtime.h>
#include <math.h>

// Problem constants (fixed by the dataset)
#define NN   20000
#define EE   320000
#define TOTE (EE + NN)
#define LDA  2048          // scratch row stride (floats)

// ---------------- device scratch (no runtime allocation allowed) ----------------
__device__ __align__(256) float g_A[(size_t)NN * 2048];   // GEMM out: [h | lin]
__device__ __align__(256) float g_H[(size_t)NN * 1024];   // layer activations
__device__ float g_as[NN * 6];
__device__ float g_ad[NN * 6];
__device__ int   g_deg[NN + 1];
__device__ int   g_off[NN + 1];
__device__ int   g_cur[NN];
__device__ int   g_csr[TOTE];

// ---------------- CSR build ----------------
__global__ void k_deg_init(int* deg, int n) {
    int i = blockIdx.x * blockDim.x + threadIdx.x;
    if (i < n) deg[i] = 1;   // self loop
}

__global__ void k_count(const int* __restrict__ ei, int E, int* deg) {
    int e = blockIdx.x * blockDim.x + threadIdx.x;
    if (e < E) atomicAdd(&deg[ei[E + e]], 1);
}

// single-block exclusive scan over 20000 ints (chunk-per-thread + block scan)
__global__ void k_scan(const int* __restrict__ deg, int* __restrict__ off, int* __restrict__ cur) {
    const int n = NN, CH = 20;           // 1024*20 = 20480 >= 20000
    int tid = threadIdx.x;
    int loc[CH];
    int base = tid * CH;
    int sum = 0;
#pragma unroll
    for (int j = 0; j < CH; j++) {
        int idx = base + j;
        int v = (idx < n) ? deg[idx] : 0;
        loc[j] = sum;
        sum += v;
    }
    int lane = tid & 31, w = tid >> 5;
    int incl = sum;
#pragma unroll
    for (int o = 1; o < 32; o <<= 1) {
        int t = __shfl_up_sync(~0u, incl, o);
        if (lane >= o) incl += t;
    }
    __shared__ int ws[32];
    if (lane == 31) ws[w] = incl;
    __syncthreads();
    if (w == 0) {
        int v = ws[lane];
#pragma unroll
        for (int o = 1; o < 32; o <<= 1) {
            int t = __shfl_up_sync(~0u, v, o);
            if (lane >= o) v += t;
        }
        ws[lane] = v;
    }
    __syncthreads();
    int warpoff = (w == 0) ? 0 : ws[w - 1];
    int excl = warpoff + incl - sum;
#pragma unroll
    for (int j = 0; j < CH; j++) {
        int idx = base + j;
        if (idx < n) { off[idx] = excl + loc[j]; cur[idx] = excl + loc[j]; }
    }
    if (tid == 1023) off[n] = warpoff + incl;
}

__global__ void k_fill(const int* __restrict__ ei, int E, int n, int* cur, int* csr) {
    int idx = blockIdx.x * blockDim.x + threadIdx.x;
    if (idx < E) {
        int s = ei[idx], d = ei[E + idx];
        int p = atomicAdd(&cur[d], 1);
        csr[p] = s;
    } else if (idx < E + n) {
        int i = idx - E;
        int p = atomicAdd(&cur[i], 1);
        csr[p] = i;
    }
}

// ---------------- SGEMM: C[M, Nw] = A[M,K] @ B[K,Nw] (+bias), C stride LDA ----------------
__global__ __launch_bounds__(256) void sgemm_k(
    const float* __restrict__ A, const float* __restrict__ B,
    float* __restrict__ C, const float* __restrict__ bias,
    int M, int K, int Nw)
{
    __shared__ float As[16][128];
    __shared__ float Bs[16][128];
    const int tid = threadIdx.x;
    const int brow = blockIdx.y * 128, bcol = blockIdx.x * 128;
    const int ty = tid >> 4, tx = tid & 15;

    float acc[8][8];
#pragma unroll
    for (int i = 0; i < 8; i++)
#pragma unroll
        for (int j = 0; j < 8; j++) acc[i][j] = 0.f;

    const int arow0 = tid >> 2;        // 0..63
    const int acol  = (tid & 3) * 4;   // 0..12
    const int brow0 = tid >> 5;        // 0..7
    const int bcc   = (tid & 31) * 4;  // 0..124

    for (int k0 = 0; k0 < K; k0 += 16) {
#pragma unroll
        for (int r = 0; r < 2; r++) {
            int ar = arow0 + r * 64;
            int grow = brow + ar;
            float4 v = make_float4(0.f, 0.f, 0.f, 0.f);
            if (grow < M) v = *(const float4*)(A + (size_t)grow * K + k0 + acol);
            As[acol + 0][ar] = v.x; As[acol + 1][ar] = v.y;
            As[acol + 2][ar] = v.z; As[acol + 3][ar] = v.w;
        }
#pragma unroll
        for (int r = 0; r < 2; r++) {
            int br = brow0 + r * 8;
            float4 v = *(const float4*)(B + (size_t)(k0 + br) * Nw + bcol + bcc);
            *(float4*)&Bs[br][bcc] = v;
        }
        __syncthreads();
#pragma unroll
        for (int k = 0; k < 16; k++) {
            float ra[8], rb[8];
#pragma unroll
            for (int i = 0; i < 4; i++) { ra[i] = As[k][ty * 4 + i]; ra[4 + i] = As[k][64 + ty * 4 + i]; }
#pragma unroll
            for (int j = 0; j < 4; j++) { rb[j] = Bs[k][tx * 4 + j]; rb[4 + j] = Bs[k][64 + tx * 4 + j]; }
#pragma unroll
            for (int i = 0; i < 8; i++)
#pragma unroll
                for (int j = 0; j < 8; j++) acc[i][j] += ra[i] * rb[j];
        }
        __syncthreads();
    }

#pragma unroll
    for (int i = 0; i < 8; i++) {
        int grow = brow + ((i < 4) ? ty * 4 + i : 64 + ty * 4 + (i - 4));
        if (grow >= M) continue;
#pragma unroll
        for (int jj = 0; jj < 2; jj++) {
            int gc = bcol + (jj ? 64 + tx * 4 : tx * 4);
            float4 v;
            v.x = acc[i][jj * 4 + 0]; v.y = acc[i][jj * 4 + 1];
            v.z = acc[i][jj * 4 + 2]; v.w = acc[i][jj * 4 + 3];
            if (bias) { v.x += bias[gc]; v.y += bias[gc + 1]; v.z += bias[gc + 2]; v.w += bias[gc + 3]; }
            *(float4*)(C + (size_t)grow * LDA + gc) = v;
        }
    }
}

// ---------------- attention coefficients: alpha_s / alpha_d per (node, head) ----------------
__global__ void k_alpha(const float* __restrict__ A, const float* __restrict__ aw_s,
                        const float* __restrict__ aw_d, float* __restrict__ os,
                        float* __restrict__ od, int n, int H)
{
    int gw = (blockIdx.x * blockDim.x + threadIdx.x) >> 5;
    int lane = threadIdx.x & 31;
    if (gw >= n * H) return;
    int node = gw / H, h = gw - node * H;
    const float4* row = (const float4*)(A + (size_t)node * LDA + h * 256);
    const float4* ws = (const float4*)(aw_s + h * 256);
    const float4* wd = (const float4*)(aw_d + h * 256);
    float s = 0.f, d = 0.f;
#pragma unroll
    for (int t = 0; t < 2; t++) {
        float4 v = row[lane + t * 32];
        float4 a = ws[lane + t * 32];
        float4 b = wd[lane + t * 32];
        s += v.x * a.x + v.y * a.y + v.z * a.z + v.w * a.w;
        d += v.x * b.x + v.y * b.y + v.z * b.z + v.w * b.w;
    }
#pragma unroll
    for (int o = 16; o; o >>= 1) {
        s += __shfl_xor_sync(~0u, s, o);
        d += __shfl_xor_sync(~0u, d, o);
    }
    if (!lane) { os[gw] = s; od[gw] = d; }
}

__device__ __forceinline__ float lrelu02(float x) { return x > 0.f ? x : 0.2f * x; }

// ---------------- edge kernel, concat layers (H=4, C=256) ----------------
// out[dst, h*256+c] = elu( sum_e alpha * hfeat[src] + lin[dst] + bias )
__global__ __launch_bounds__(256) void k_edge_cat(
    const float* __restrict__ A,       // [N, 2048]: h in cols 0..1023, lin in 1024..2047
    const float* __restrict__ as_, const float* __restrict__ ad_,
    const int* __restrict__ off, const int* __restrict__ csr,
    const float* __restrict__ bias, float* __restrict__ out)
{
    const int H = 4;
    int dst = blockIdx.x;
    int tid = threadIdx.x;
    int head = tid >> 6, l = tid & 63;   // 64 threads per head, 4 channels each (float4)
    int s = off[dst], e = off[dst + 1];
    float ad = ad_[dst * H + head];

    __shared__ float red[8];
    int w = tid >> 5;

    // pass 1: per-head max
    float m = -INFINITY;
    for (int i = s + l; i < e; i += 64)
        m = fmaxf(m, lrelu02(as_[csr[i] * H + head] + ad));
#pragma unroll
    for (int o = 16; o; o >>= 1) m = fmaxf(m, __shfl_xor_sync(~0u, m, o));
    if ((tid & 31) == 0) red[w] = m;
    __syncthreads();
    m = fmaxf(red[head * 2], red[head * 2 + 1]);
    __syncthreads();

    // pass 2: per-head sum of exp
    float ssum = 0.f;
    for (int i = s + l; i < e; i += 64)
        ssum += __expf(lrelu02(as_[csr[i] * H + head] + ad) - m);
#pragma unroll
    for (int o = 16; o; o >>= 1) ssum += __shfl_xor_sync(~0u, ssum, o);
    if ((tid & 31) == 0) red[w] = ssum;
    __syncthreads();
    float inv = 1.0f / (red[head * 2] + red[head * 2 + 1] + 1e-16f);

    // pass 3: weighted accumulation (chunks of 64 edges, weights staged in smem)
    __shared__ float wsm[4][64];
    __shared__ int ssm[64];
    float4 acc = make_float4(0.f, 0.f, 0.f, 0.f);
    for (int base = s; base < e; base += 64) {
        __syncthreads();
        int i = base + l;
        if (i < e) {
            int src = csr[i];
            float v = lrelu02(as_[src * H + head] + ad);
            wsm[head][l] = __expf(v - m) * inv;
            if (head == 0) ssm[l] = src;
        }
        __syncthreads();
        int cnt = min(64, e - base);
        for (int j = 0; j < cnt; j++) {
            float wgt = wsm[head][j];
            float4 v = *(const float4*)(A + (size_t)ssm[j] * LDA + head * 256 + l * 4);
            acc.x += wgt * v.x; acc.y += wgt * v.y;
            acc.z += wgt * v.z; acc.w += wgt * v.w;
        }
    }

    int oc = head * 256 + l * 4;
    float4 lin = *(const float4*)(A + (size_t)dst * LDA + 1024 + oc);
    float4 r;
    r.x = acc.x + lin.x + bias[oc + 0];
    r.y = acc.y + lin.y + bias[oc + 1];
    r.z = acc.z + lin.z + bias[oc + 2];
    r.w = acc.w + lin.w + bias[oc + 3];
    r.x = r.x > 0.f ? r.x : expm1f(r.x);
    r.y = r.y > 0.f ? r.y : expm1f(r.y);
    r.z = r.z > 0.f ? r.z : expm1f(r.z);
    r.w = r.w > 0.f ? r.w : expm1f(r.w);
    *(float4*)(out + (size_t)dst * 1024 + oc) = r;
}

// ---------------- edge kernel, mean layer (H=6, C=256), final output ----------------
__global__ __launch_bounds__(256) void k_edge_mean(
    const float* __restrict__ A,       // h in cols 0..1535, lin in 1536..1791
    const float* __restrict__ as_, const float* __restrict__ ad_,
    const int* __restrict__ off, const int* __restrict__ csr,
    const float* __restrict__ bias, float* __restrict__ out)
{
    const int H = 6;
    int dst = blockIdx.x;                  // grid = 16384 (only rows needed)
    int tid = threadIdx.x;                 // channel c = tid
    int s = off[dst], e = off[dst + 1];

    __shared__ float m_s[6], inv_s[6], adsh[6];
    int w = tid >> 5, lane = tid & 31;

    if (w < 6) {
        float ad = ad_[dst * H + w];
        float m = -INFINITY;
        for (int i = s + lane; i < e; i += 32)
            m = fmaxf(m, lrelu02(as_[csr[i] * H + w] + ad));
#pragma unroll
        for (int o = 16; o; o >>= 1) m = fmaxf(m, __shfl_xor_sync(~0u, m, o));
        float ss = 0.f;
        for (int i = s + lane; i < e; i += 32)
            ss += __expf(lrelu02(as_[csr[i] * H + w] + ad) - m);
#pragma unroll
        for (int o = 16; o; o >>= 1) ss += __shfl_xor_sync(~0u, ss, o);
        if (lane == 0) { m_s[w] = m; inv_s[w] = 1.0f / (ss + 1e-16f); adsh[w] = ad; }
    }
    __syncthreads();

    float acc[6] = {0.f, 0.f, 0.f, 0.f, 0.f, 0.f};
    __shared__ float wsm[6][64];
    __shared__ int ssm[64];
    for (int base = s; base < e; base += 64) {
        __syncthreads();
        for (int k = tid; k < 6 * 64; k += 256) {
            int h = k >> 6, j = k & 63;
            int i = base + j;
            if (i < e) {
                int src = csr[i];
                float v = lrelu02(as_[src * H + h] + adsh[h]);
                wsm[h][j] = __expf(v - m_s[h]) * inv_s[h];
                if (h == 0) ssm[j] = src;
            }
        }
        __syncthreads();
        int cnt = min(64, e - base);
        for (int j = 0; j < cnt; j++) {
            const float* row = A + (size_t)ssm[j] * LDA + tid;
#pragma unroll
            for (int h = 0; h < 6; h++) acc[h] += wsm[h][j] * row[h * 256];
        }
    }

    float r = (acc[0] + acc[1] + acc[2] + acc[3] + acc[4] + acc[5]) * (1.0f / 6.0f)
            + bias[tid] + A[(size_t)dst * LDA + 1536 + tid];
    out[(size_t)dst * 256 + tid] = r;
}

// ---------------- launch ----------------
extern "C" void kernel_launch(void* const* d_in, const int* in_sizes, int n_in,
                              void* d_out, int out_size)
{
    const float* x  = (const float*)d_in[0];
    const int*   ei = (const int*)d_in[1];
    // original_size may or may not appear as a tiny scalar input at index 2
    int base = (in_sizes[2] <= 16) ? 3 : 2;
    const float* W1  = (const float*)d_in[base + 0];
    const float* as1 = (const float*)d_in[base + 1];
    const float* ad1 = (const float*)d_in[base + 2];
    const float* b1  = (const float*)d_in[base + 3];
    const float* lw1 = (const float*)d_in[base + 4];
    const float* lb1 = (const float*)d_in[base + 5];
    const float* W2  = (const float*)d_in[base + 6];
    const float* as2 = (const float*)d_in[base + 7];
    const float* ad2 = (const float*)d_in[base + 8];
    const float* b2  = (const float*)d_in[base + 9];
    const float* lw2 = (const float*)d_in[base + 10];
    const float* lb2 = (const float*)d_in[base + 11];
    const float* W3  = (const float*)d_in[base + 12];
    const float* as3 = (const float*)d_in[base + 13];
    const float* ad3 = (const float*)d_in[base + 14];
    const float* b3  = (const float*)d_in[base + 15];
    const float* lw3 = (const float*)d_in[base + 16];
    const float* lb3 = (const float*)d_in[base + 17];

    const int N = NN;
    const int E = in_sizes[1] / 2;

    float *pA, *pH, *pas, *pad;
    int *pdeg, *poff, *pcur, *pcsr;
    cudaGetSymbolAddress((void**)&pA, g_A);
    cudaGetSymbolAddress((void**)&pH, g_H);
    cudaGetSymbolAddress((void**)&pas, g_as);
    cudaGetSymbolAddress((void**)&pad, g_ad);
    cudaGetSymbolAddress((void**)&pdeg, g_deg);
    cudaGetSymbolAddress((void**)&poff, g_off);
    cudaGetSymbolAddress((void**)&pcur, g_cur);
    cudaGetSymbolAddress((void**)&pcsr, g_csr);

    // CSR build (dst-sorted, self loops included)
    k_deg_init<<<(N + 255) / 256, 256>>>(pdeg, N);
    k_count<<<(E + 255) / 256, 256>>>(ei, E, pdeg);
    k_scan<<<1, 1024>>>(pdeg, poff, pcur);
    k_fill<<<(E + N + 255) / 256, 256>>>(ei, E, N, pcur, pcsr);

    dim3 g8(8, 157), g12(12, 157), g2(2, 157);

    // ---- layer 1 (in: x [N,512]) ----
    sgemm_k<<<g8, 256>>>(x, W1, pA, nullptr, N, 512, 1024);
    sgemm_k<<<g8, 256>>>(x, lw1, pA + 1024, lb1, N, 512, 1024);
    k_alpha<<<(N * 4 + 7) / 8, 256>>>(pA, as1, ad1, pas, pad, N, 4);
    k_edge_cat<<<N, 256>>>(pA, pas, pad, poff, pcsr, b1, pH);

    // ---- layer 2 (in: pH [N,1024]) ----
    sgemm_k<<<g8, 256>>>(pH, W2, pA, nullptr, N, 1024, 1024);
    sgemm_k<<<g8, 256>>>(pH, lw2, pA + 1024, lb2, N, 1024, 1024);
    k_alpha<<<(N * 4 + 7) / 8, 256>>>(pA, as2, ad2, pas, pad, N, 4);
    k_edge_cat<<<N, 256>>>(pA, pas, pad, poff, pcsr, b2, pH);

    // ---- layer 3 (in: pH [N,1024], mean over 6 heads, output 16384 rows) ----
    sgemm_k<<<g12, 256>>>(pH, W3, pA, nullptr, N, 1024, 1536);
    sgemm_k<<<g2, 256>>>(pH, lw3, pA + 1536, lb3, N, 1024, 256);
    k_alpha<<<(N * 6 + 7) / 8, 256>>>(pA, as3, ad3, pas, pad, N, 6);
    k_edge_mean<<<16384, 256>>>(pA, pas, pad, poff, pcsr, b3, (float*)d_out);
}

// round 6
// speedup vs baseline: 1.0029x; 1.0029x over previous
#include <cuda_runtime.h>
#include <math.h>

// Problem constants (fixed by the dataset)
#define NN   20000
#define EE   320000
#define TOTE (EE + NN)
#define LDA  2048          // scratch row stride (floats)

// ---------------- device scratch (no runtime allocation allowed) ----------------
__device__ __align__(256) float g_A[(size_t)NN * 2048];   // GEMM out: [h | lin]
__device__ __align__(256) float g_H[(size_t)NN * 1024];   // layer activations
__device__ float g_as[NN * 6];
__device__ float g_ad[NN * 6];
__device__ int   g_deg[NN + 1];
__device__ int   g_off[NN + 1];
__device__ int   g_cur[NN];
__device__ int   g_csr[TOTE];

// ---------------- CSR build ----------------
__global__ void k_deg_init(int* deg, int n) {
    int i = blockIdx.x * blockDim.x + threadIdx.x;
    if (i < n) deg[i] = 1;   // self loop
}

__global__ void k_count(const int* __restrict__ ei, int E, int* deg) {
    int e = blockIdx.x * blockDim.x + threadIdx.x;
    if (e < E) atomicAdd(&deg[ei[E + e]], 1);
}

// single-block exclusive scan over 20000 ints (chunk-per-thread + block scan)
__global__ void k_scan(const int* __restrict__ deg, int* __restrict__ off, int* __restrict__ cur) {
    const int n = NN, CH = 20;           // 1024*20 = 20480 >= 20000
    int tid = threadIdx.x;
    int loc[CH];
    int base = tid * CH;
    int sum = 0;
#pragma unroll
    for (int j = 0; j < CH; j++) {
        int idx = base + j;
        int v = (idx < n) ? deg[idx] : 0;
        loc[j] = sum;
        sum += v;
    }
    int lane = tid & 31, w = tid >> 5;
    int incl = sum;
#pragma unroll
    for (int o = 1; o < 32; o <<= 1) {
        int t = __shfl_up_sync(~0u, incl, o);
        if (lane >= o) incl += t;
    }
    __shared__ int ws[32];
    if (lane == 31) ws[w] = incl;
    __syncthreads();
    if (w == 0) {
        int v = ws[lane];
#pragma unroll
        for (int o = 1; o < 32; o <<= 1) {
            int t = __shfl_up_sync(~0u, v, o);
            if (lane >= o) v += t;
        }
        ws[lane] = v;
    }
    __syncthreads();
    int warpoff = (w == 0) ? 0 : ws[w - 1];
    int excl = warpoff + incl - sum;
#pragma unroll
    for (int j = 0; j < CH; j++) {
        int idx = base + j;
        if (idx < n) { off[idx] = excl + loc[j]; cur[idx] = excl + loc[j]; }
    }
    if (tid == 1023) off[n] = warpoff + incl;
}

__global__ void k_fill(const int* __restrict__ ei, int E, int n, int* cur, int* csr) {
    int idx = blockIdx.x * blockDim.x + threadIdx.x;
    if (idx < E) {
        int s = ei[idx], d = ei[E + idx];
        int p = atomicAdd(&cur[d], 1);
        csr[p] = s;
    } else if (idx < E + n) {
        int i = idx - E;
        int p = atomicAdd(&cur[i], 1);
        csr[p] = i;
    }
}

// ---------------- SGEMM: C[M, Nw] = A[M,K] @ B[K,Nw] (+bias), C stride LDA ----------------
__global__ __launch_bounds__(256) void sgemm_k(
    const float* __restrict__ A, const float* __restrict__ B,
    float* __restrict__ C, const float* __restrict__ bias,
    int M, int K, int Nw)
{
    __shared__ float As[16][128];
    __shared__ float Bs[16][128];
    const int tid = threadIdx.x;
    const int brow = blockIdx.y * 128, bcol = blockIdx.x * 128;
    const int ty = tid >> 4, tx = tid & 15;

    float acc[8][8];
#pragma unroll
    for (int i = 0; i < 8; i++)
#pragma unroll
        for (int j = 0; j < 8; j++) acc[i][j] = 0.f;

    const int arow0 = tid >> 2;        // 0..63
    const int acol  = (tid & 3) * 4;   // 0..12
    const int brow0 = tid >> 5;        // 0..7
    const int bcc   = (tid & 31) * 4;  // 0..124

    for (int k0 = 0; k0 < K; k0 += 16) {
#pragma unroll
        for (int r = 0; r < 2; r++) {
            int ar = arow0 + r * 64;
            int grow = brow + ar;
            float4 v = make_float4(0.f, 0.f, 0.f, 0.f);
            if (grow < M) v = *(const float4*)(A + (size_t)grow * K + k0 + acol);
            As[acol + 0][ar] = v.x; As[acol + 1][ar] = v.y;
            As[acol + 2][ar] = v.z; As[acol + 3][ar] = v.w;
        }
#pragma unroll
        for (int r = 0; r < 2; r++) {
            int br = brow0 + r * 8;
            float4 v = *(const float4*)(B + (size_t)(k0 + br) * Nw + bcol + bcc);
            *(float4*)&Bs[br][bcc] = v;
        }
        __syncthreads();
#pragma unroll
        for (int k = 0; k < 16; k++) {
            float ra[8], rb[8];
#pragma unroll
            for (int i = 0; i < 4; i++) { ra[i] = As[k][ty * 4 + i]; ra[4 + i] = As[k][64 + ty * 4 + i]; }
#pragma unroll
            for (int j = 0; j < 4; j++) { rb[j] = Bs[k][tx * 4 + j]; rb[4 + j] = Bs[k][64 + tx * 4 + j]; }
#pragma unroll
            for (int i = 0; i < 8; i++)
#pragma unroll
                for (int j = 0; j < 8; j++) acc[i][j] += ra[i] * rb[j];
        }
        __syncthreads();
    }

#pragma unroll
    for (int i = 0; i < 8; i++) {
        int grow = brow + ((i < 4) ? ty * 4 + i : 64 + ty * 4 + (i - 4));
        if (grow >= M) continue;
#pragma unroll
        for (int jj = 0; jj < 2; jj++) {
            int gc = bcol + (jj ? 64 + tx * 4 : tx * 4);
            float4 v;
            v.x = acc[i][jj * 4 + 0]; v.y = acc[i][jj * 4 + 1];
            v.z = acc[i][jj * 4 + 2]; v.w = acc[i][jj * 4 + 3];
            if (bias) { v.x += bias[gc]; v.y += bias[gc + 1]; v.z += bias[gc + 2]; v.w += bias[gc + 3]; }
            *(float4*)(C + (size_t)grow * LDA + gc) = v;
        }
    }
}

// ---------------- attention coefficients: alpha_s / alpha_d per (node, head) ----------------
__global__ void k_alpha(const float* __restrict__ A, const float* __restrict__ aw_s,
                        const float* __restrict__ aw_d, float* __restrict__ os,
                        float* __restrict__ od, int n, int H)
{
    int gw = (blockIdx.x * blockDim.x + threadIdx.x) >> 5;
    int lane = threadIdx.x & 31;
    if (gw >= n * H) return;
    int node = gw / H, h = gw - node * H;
    const float4* row = (const float4*)(A + (size_t)node * LDA + h * 256);
    const float4* ws = (const float4*)(aw_s + h * 256);
    const float4* wd = (const float4*)(aw_d + h * 256);
    float s = 0.f, d = 0.f;
#pragma unroll
    for (int t = 0; t < 2; t++) {
        float4 v = row[lane + t * 32];
        float4 a = ws[lane + t * 32];
        float4 b = wd[lane + t * 32];
        s += v.x * a.x + v.y * a.y + v.z * a.z + v.w * a.w;
        d += v.x * b.x + v.y * b.y + v.z * b.z + v.w * b.w;
    }
#pragma unroll
    for (int o = 16; o; o >>= 1) {
        s += __shfl_xor_sync(~0u, s, o);
        d += __shfl_xor_sync(~0u, d, o);
    }
    if (!lane) { os[gw] = s; od[gw] = d; }
}

__device__ __forceinline__ float lrelu02(float x) { return x > 0.f ? x : 0.2f * x; }

// ---------------- edge kernel, concat layers (H=4, C=256) ----------------
// out[dst, h*256+c] = elu( sum_e alpha * hfeat[src] + lin[dst] + bias )
__global__ __launch_bounds__(256) void k_edge_cat(
    const float* __restrict__ A,       // [N, 2048]: h in cols 0..1023, lin in 1024..2047
    const float* __restrict__ as_, const float* __restrict__ ad_,
    const int* __restrict__ off, const int* __restrict__ csr,
    const float* __restrict__ bias, float* __restrict__ out)
{
    const int H = 4;
    int dst = blockIdx.x;
    int tid = threadIdx.x;
    int head = tid >> 6, l = tid & 63;   // 64 threads per head, 4 channels each (float4)
    int s = off[dst], e = off[dst + 1];
    float ad = ad_[dst * H + head];

    __shared__ float red[8];
    int w = tid >> 5;

    // pass 1: per-head max
    float m = -INFINITY;
    for (int i = s + l; i < e; i += 64)
        m = fmaxf(m, lrelu02(as_[csr[i] * H + head] + ad));
#pragma unroll
    for (int o = 16; o; o >>= 1) m = fmaxf(m, __shfl_xor_sync(~0u, m, o));
    if ((tid & 31) == 0) red[w] = m;
    __syncthreads();
    m = fmaxf(red[head * 2], red[head * 2 + 1]);
    __syncthreads();

    // pass 2: per-head sum of exp
    float ssum = 0.f;
    for (int i = s + l; i < e; i += 64)
        ssum += __expf(lrelu02(as_[csr[i] * H + head] + ad) - m);
#pragma unroll
    for (int o = 16; o; o >>= 1) ssum += __shfl_xor_sync(~0u, ssum, o);
    if ((tid & 31) == 0) red[w] = ssum;
    __syncthreads();
    float inv = 1.0f / (red[head * 2] + red[head * 2 + 1] + 1e-16f);

    // pass 3: weighted accumulation (chunks of 64 edges, weights staged in smem)
    __shared__ float wsm[4][64];
    __shared__ int ssm[64];
    float4 acc = make_float4(0.f, 0.f, 0.f, 0.f);
    for (int base = s; base < e; base += 64) {
        __syncthreads();
        int i = base + l;
        if (i < e) {
            int src = csr[i];
            float v = lrelu02(as_[src * H + head] + ad);
            wsm[head][l] = __expf(v - m) * inv;
            if (head == 0) ssm[l] = src;
        }
        __syncthreads();
        int cnt = min(64, e - base);
        for (int j = 0; j < cnt; j++) {
            float wgt = wsm[head][j];
            float4 v = *(const float4*)(A + (size_t)ssm[j] * LDA + head * 256 + l * 4);
            acc.x += wgt * v.x; acc.y += wgt * v.y;
            acc.z += wgt * v.z; acc.w += wgt * v.w;
        }
    }

    int oc = head * 256 + l * 4;
    float4 lin = *(const float4*)(A + (size_t)dst * LDA + 1024 + oc);
    float4 r;
    r.x = acc.x + lin.x + bias[oc + 0];
    r.y = acc.y + lin.y + bias[oc + 1];
    r.z = acc.z + lin.z + bias[oc + 2];
    r.w = acc.w + lin.w + bias[oc + 3];
    r.x = r.x > 0.f ? r.x : expm1f(r.x);
    r.y = r.y > 0.f ? r.y : expm1f(r.y);
    r.z = r.z > 0.f ? r.z : expm1f(r.z);
    r.w = r.w > 0.f ? r.w : expm1f(r.w);
    *(float4*)(out + (size_t)dst * 1024 + oc) = r;
}

// ---------------- edge kernel, mean layer (H=6, C=256), final output ----------------
__global__ __launch_bounds__(256) void k_edge_mean(
    const float* __restrict__ A,       // h in cols 0..1535, lin in 1536..1791
    const float* __restrict__ as_, const float* __restrict__ ad_,
    const int* __restrict__ off, const int* __restrict__ csr,
    const float* __restrict__ bias, float* __restrict__ out)
{
    const int H = 6;
    int dst = blockIdx.x;                  // grid = 16384 (only rows needed)
    int tid = threadIdx.x;                 // channel c = tid
    int s = off[dst], e = off[dst + 1];

    __shared__ float m_s[6], inv_s[6], adsh[6];
    int w = tid >> 5, lane = tid & 31;

    if (w < 6) {
        float ad = ad_[dst * H + w];
        float m = -INFINITY;
        for (int i = s + lane; i < e; i += 32)
            m = fmaxf(m, lrelu02(as_[csr[i] * H + w] + ad));
#pragma unroll
        for (int o = 16; o; o >>= 1) m = fmaxf(m, __shfl_xor_sync(~0u, m, o));
        float ss = 0.f;
        for (int i = s + lane; i < e; i += 32)
            ss += __expf(lrelu02(as_[csr[i] * H + w] + ad) - m);
#pragma unroll
        for (int o = 16; o; o >>= 1) ss += __shfl_xor_sync(~0u, ss, o);
        if (lane == 0) { m_s[w] = m; inv_s[w] = 1.0f / (ss + 1e-16f); adsh[w] = ad; }
    }
    __syncthreads();

    float acc[6] = {0.f, 0.f, 0.f, 0.f, 0.f, 0.f};
    __shared__ float wsm[6][64];
    __shared__ int ssm[64];
    for (int base = s; base < e; base += 64) {
        __syncthreads();
        for (int k = tid; k < 6 * 64; k += 256) {
            int h = k >> 6, j = k & 63;
            int i = base + j;
            if (i < e) {
                int src = csr[i];
                float v = lrelu02(as_[src * H + h] + adsh[h]);
                wsm[h][j] = __expf(v - m_s[h]) * inv_s[h];
                if (h == 0) ssm[j] = src;
            }
        }
        __syncthreads();
        int cnt = min(64, e - base);
        for (int j = 0; j < cnt; j++) {
            const float* row = A + (size_t)ssm[j] * LDA + tid;
#pragma unroll
            for (int h = 0; h < 6; h++) acc[h] += wsm[h][j] * row[h * 256];
        }
    }

    float r = (acc[0] + acc[1] + acc[2] + acc[3] + acc[4] + acc[5]) * (1.0f / 6.0f)
            + bias[tid] + A[(size_t)dst * LDA + 1536 + tid];
    out[(size_t)dst * 256 + tid] = r;
}

// ---------------- launch ----------------
extern "C" void kernel_launch(void* const* d_in, const int* in_sizes, int n_in,
                              void* d_out, int out_size)
{
    const float* x  = (const float*)d_in[0];
    const int*   ei = (const int*)d_in[1];
    // original_size may or may not appear as a tiny scalar input at index 2
    int base = (in_sizes[2] <= 16) ? 3 : 2;
    const float* W1  = (const float*)d_in[base + 0];
    const float* as1 = (const float*)d_in[base + 1];
    const float* ad1 = (const float*)d_in[base + 2];
    const float* b1  = (const float*)d_in[base + 3];
    const float* lw1 = (const float*)d_in[base + 4];
    const float* lb1 = (const float*)d_in[base + 5];
    const float* W2  = (const float*)d_in[base + 6];
    const float* as2 = (const float*)d_in[base + 7];
    const float* ad2 = (const float*)d_in[base + 8];
    const float* b2  = (const float*)d_in[base + 9];
    const float* lw2 = (const float*)d_in[base + 10];
    const float* lb2 = (const float*)d_in[base + 11];
    const float* W3  = (const float*)d_in[base + 12];
    const float* as3 = (const float*)d_in[base + 13];
    const float* ad3 = (const float*)d_in[base + 14];
    const float* b3  = (const float*)d_in[base + 15];
    const float* lw3 = (const float*)d_in[base + 16];
    const float* lb3 = (const float*)d_in[base + 17];

    const int N = NN;
    const int E = in_sizes[1] / 2;

    float *pA, *pH, *pas, *pad;
    int *pdeg, *poff, *pcur, *pcsr;
    cudaGetSymbolAddress((void**)&pA, g_A);
    cudaGetSymbolAddress((void**)&pH, g_H);
    cudaGetSymbolAddress((void**)&pas, g_as);
    cudaGetSymbolAddress((void**)&pad, g_ad);
    cudaGetSymbolAddress((void**)&pdeg, g_deg);
    cudaGetSymbolAddress((void**)&poff, g_off);
    cudaGetSymbolAddress((void**)&pcur, g_cur);
    cudaGetSymbolAddress((void**)&pcsr, g_csr);

    // CSR build (dst-sorted, self loops included)
    k_deg_init<<<(N + 255) / 256, 256>>>(pdeg, N);
    k_count<<<(E + 255) / 256, 256>>>(ei, E, pdeg);
    k_scan<<<1, 1024>>>(pdeg, poff, pcur);
    k_fill<<<(E + N + 255) / 256, 256>>>(ei, E, N, pcur, pcsr);

    dim3 g8(8, 157), g12(12, 157), g2(2, 157);

    // ---- layer 1 (in: x [N,512]) ----
    sgemm_k<<<g8, 256>>>(x, W1, pA, nullptr, N, 512, 1024);
    sgemm_k<<<g8, 256>>>(x, lw1, pA + 1024, lb1, N, 512, 1024);
    k_alpha<<<(N * 4 + 7) / 8, 256>>>(pA, as1, ad1, pas, pad, N, 4);
    k_edge_cat<<<N, 256>>>(pA, pas, pad, poff, pcsr, b1, pH);

    // ---- layer 2 (in: pH [N,1024]) ----
    sgemm_k<<<g8, 256>>>(pH, W2, pA, nullptr, N, 1024, 1024);
    sgemm_k<<<g8, 256>>>(pH, lw2, pA + 1024, lb2, N, 1024, 1024);
    k_alpha<<<(N * 4 + 7) / 8, 256>>>(pA, as2, ad2, pas, pad, N, 4);
    k_edge_cat<<<N, 256>>>(pA, pas, pad, poff, pcsr, b2, pH);

    // ---- layer 3 (in: pH [N,1024], mean over 6 heads, output 16384 rows) ----
    sgemm_k<<<g12, 256>>>(pH, W3, pA, nullptr, N, 1024, 1536);
    sgemm_k<<<g2, 256>>>(pH, lw3, pA + 1536, lb3, N, 1024, 256);
    k_alpha<<<(N * 6 + 7) / 8, 256>>>(pA, as3, ad3, pas, pad, N, 6);
    k_edge_mean<<<16384, 256>>>(pA, pas, pad, poff, pcsr, b3, (float*)d_out);
}